// round 17
// baseline (speedup 1.0000x reference)
#include <cuda_runtime.h>
#include <cuda_bf16.h>

// ---------------------------------------------------------------------------
// Compile-time D4 codebook (values stored as integers = 2*g, in {±1,±3,±5}),
// replicated exactly from the reference _code8_to_d4 builder.
// ---------------------------------------------------------------------------
__host__ __device__ constexpr int cw2(int i8, int j) {
    int v[4] = {0, 0, 0, 0};
    int b = i8 & 31;
    if (b < 16) {
        if (b < 8) {
            if (b < 2) {
                if (b < 1) { v[0] = 1; v[1] = 1; v[2] = 1; v[3] = 1; }
                else       { v[0] = 3; v[1] = 3; v[2] = 3; v[3] = 3; }
            } else {
                int ibx = b >> 1;
                if (b & 1) { v[0] = 1; v[1] = 1; v[2] = 1; v[3] = 1; v[0] = 3; v[ibx] = 3; }
                else       { v[0] = 3; v[1] = 3; v[2] = 3; v[3] = 3; v[0] = 1; v[ibx] = 1; }
            }
        } else {
            int ibx = b & 3;
            if (b < 12) { v[0] = 1; v[1] = 1; v[2] = 1; v[3] = 1; v[ibx] = 3; }
            else        { v[0] = 3; v[1] = 3; v[2] = 3; v[3] = 3; v[ibx] = 1; }
        }
    } else if (b < 20) {
        int ibx = b & 3;
        v[0] = 1; v[1] = 1; v[2] = 1; v[3] = 1; v[ibx] = 5;
    } else {
        int ibx = b - 20;
        int ib4 = ibx & 3;
        int ib3 = ibx >> 2;
        v[0] = 1; v[1] = 1; v[2] = 1; v[3] = 1;
        v[ib4] = 3;
        if (ib3 >= ib4) ib3 += 1;
        v[ib3] = 5;
    }
    if (i8 & 32) v[2] = -v[2];
    if (i8 & 64) v[1] = -v[1];
    int s = v[0] + v[1] + v[2] + v[3];   // 2 * sum(x), always even
    int sumx = s / 2;
    if (sumx & 1) v[3] = -v[3];
    if (i8 & 128) { v[0] = -v[0]; v[1] = -v[1]; v[2] = -v[2]; v[3] = -v[3]; }
    return v[j];
}

__host__ __device__ constexpr int cnorm(int i8) {
    int s = 0;
    for (int j = 0; j < 4; j++) { int v = cw2(i8, j); s += v * v; }
    return s / 4;   // |g|^2 in {1,3,5,7,9}, exact
}

// ---- codeword float table for the exact slow path --------------------------
struct F4 { float x, y, z, w; };
struct G4 { F4 v[128]; };
__host__ __device__ constexpr G4 mkf4() {
    G4 t{};
    for (int k = 0; k < 128; k++) {
        t.v[k].x = (float)cw2(k, 0) * 0.5f;
        t.v[k].y = (float)cw2(k, 1) * 0.5f;
        t.v[k].z = (float)cw2(k, 2) * 0.5f;
        t.v[k].w = (float)cw2(k, 3) * 0.5f;
    }
    return t;
}
__device__ __align__(16) const G4 g_f4 = mkf4();

struct NN { float v[32]; };
__host__ __device__ constexpr NN mknn() {
    NN t{};
    for (int P = 0; P < 32; P++) t.v[P] = -(float)cnorm(P);
    return t;
}
__device__ const NN g_nn = mknn();

// ---- inverse table: (mag-codes, sign bits) -> codebook index ---------------
// per coord: m in {0,1,2} for |g| in {0.5,1.5,2.5}; cm = sum m_j << 2j (8 bits)
// sb = sum sign_j << j (4 bits). inv[cm | sb<<8] = k. Bijective on the 256
// valid codes; unused slots stay 0 and are never queried.
struct IT { unsigned char v[4096]; };
__host__ __device__ constexpr IT mkinv() {
    IT t{};
    for (int k = 0; k < 256; k++) {
        unsigned cm = 0, sb = 0;
        for (int j = 0; j < 4; j++) {
            int c2 = cw2(k, j);
            int a = c2 < 0 ? -c2 : c2;
            cm |= (unsigned)((a - 1) / 2) << (2 * j);
            sb |= (unsigned)(c2 < 0 ? 1 : 0) << j;
        }
        t.v[cm | (sb << 8)] = (unsigned char)k;
    }
    return t;
}
__device__ const IT g_inv = mkinv();

// ---------------------------------------------------------------------------
// Exact slow path (rare): reference-chain scan over all 32 patterns x 4
// variants, then exact recovery with ascending-index tie order. This is the
// R9 code path that measured rel_err = 0.0.
// ---------------------------------------------------------------------------
__device__ __noinline__ int slow_exact(float4 x) {
    const float4* gt = reinterpret_cast<const float4*>(g_f4.v);
    float bs = -3.0e38f;
    int bp = 0;
#pragma unroll 1
    for (int P = 0; P < 32; P++) {
        float gm = 0.0f;
#pragma unroll
        for (int v = 0; v < 4; v++) {
            float4 g = gt[P + (v << 5)];
            float d = x.x * g.x;
            d = fmaf(x.y, g.y, d);
            d = fmaf(x.z, g.z, d);
            d = fmaf(x.w, g.w, d);
            gm = fmaxf(gm, fabsf(d));
        }
        float s = fmaf(gm, 2.0f, g_nn.v[P]);
        if (s > bs) { bs = s; bp = P; }   // strict >: lowest pattern wins ties
    }
    float dv[4];
#pragma unroll
    for (int v = 0; v < 4; v++) {
        float4 g = gt[bp + (v << 5)];
        float d = x.x * g.x;
        d = fmaf(x.y, g.y, d);
        d = fmaf(x.z, g.z, d);
        d = fmaf(x.w, g.w, d);
        dv[v] = d;
    }
    float gmr = fmaxf(fmaxf(fabsf(dv[0]), fabsf(dv[1])),
                      fmaxf(fabsf(dv[2]), fabsf(dv[3])));
    int kk = bp;
    bool found = false;
#pragma unroll
    for (int v = 0; v < 4; v++) {
        bool hit = (!found) && (fabsf(dv[v]) == gmr);
        if (hit) kk = (bp + (v << 5)) | ((dv[v] < 0.0f) ? 128 : 0);
        found = found || hit;
    }
    return kk;
}

// compare-exchange (descending) on index-tagged magnitude uints
#define CE_DESC(p, q) { unsigned _hi = max(p, q), _lo = min(p, q); p = _hi; q = _lo; }

// ---------------------------------------------------------------------------
// Fast path for one vector (verbatim from the R12 kernel that measured
// rel_err 0.0). Returns the candidate index; sets bad when the δ-guard or
// the sort-tie/zero guard requires the exact slow path.
// ---------------------------------------------------------------------------
__device__ __forceinline__ int fast_kk(float4 x, bool& bad) {
    unsigned ux0 = __float_as_uint(x.x);
    unsigned ux1 = __float_as_uint(x.y);
    unsigned ux2 = __float_as_uint(x.z);
    unsigned ux3 = __float_as_uint(x.w);

    // |x| with low 2 mantissa bits replaced by the coordinate index
    unsigned t0 = (ux0 & 0x7FFFFFFCu) | 0u;
    unsigned t1 = (ux1 & 0x7FFFFFFCu) | 1u;
    unsigned t2 = (ux2 & 0x7FFFFFFCu) | 2u;
    unsigned t3 = (ux3 & 0x7FFFFFFCu) | 3u;

    // sort descending: t0 >= t1 >= t2 >= t3 (positive floats == uint order)
    CE_DESC(t0, t1); CE_DESC(t2, t3); CE_DESC(t0, t2); CE_DESC(t1, t3); CE_DESC(t1, t2);

    float y1 = __uint_as_float(t0 & ~3u);
    float y2 = __uint_as_float(t1 & ~3u);
    float y3 = __uint_as_float(t2 & ~3u);
    float y4 = __uint_as_float(t3 & ~3u);

    // parity of negative-coordinate count
    unsigned parbit = ((ux0 ^ ux1) ^ (ux2 ^ ux3)) >> 31;

    // shared partial sums
    float q34  = y3 + y4;
    float q12  = y1 + y2;
    float q234 = y2 + q34;
    float T    = y1 + q234;
    float y123 = q12 + y3;

    // parity penalty activations (u = y4 when this parity class is "wrong")
    float u0 = parbit ? y4 : 0.0f;   // multisets with even #1.5 (bsel=0)
    float u1 = parbit ? 0.0f : y4;   // multisets with odd  #1.5 (bsel=1)

    // 7 multiset halfscores, offset +32 so all are positive:
    //   sh = sum(m_r * y_r) - penalty + (32 - n/2)
    float sh0 = fmaf(0.5f, T, 31.5f - u0);                                   // {.5^4}
    float sh1 = fmaf(1.5f, T, fmaf(-3.0f, u0, 27.5f));                       // {1.5^4}
    float sh2 = fmaf(1.5f, q12, fmaf(0.5f, q34, 29.5f - u0));                // {1.5^2,.5^2}
    float sh3 = fmaf(1.5f, y1, fmaf(0.5f, q234, 30.5f - u1));                // {1.5,.5^3}
    float sh4 = fmaf(1.5f, y123, fmaf(0.5f, y4, 28.5f - u1));                // {1.5^3,.5}
    float sh5 = fmaf(2.5f, y1, fmaf(0.5f, q234, 28.5f - u0));                // {2.5,.5^3}
    float sh6 = fmaf(2.5f, y1, fmaf(1.5f, y2, fmaf(0.5f, q34, 27.5f - u1))); // {2.5,1.5,.5^2}

    // argmax with 3-bit id packed into the mantissa; track best + second
    unsigned best = 0u, second = 0u;
    {
        float sh[7] = {sh0, sh1, sh2, sh3, sh4, sh5, sh6};
#pragma unroll
        for (int m = 0; m < 7; m++) {
            unsigned u = (__float_as_uint(sh[m]) & 0xFFFFFFF8u) | (unsigned)m;
            unsigned t = min(u, best);
            second = max(second, t);
            best   = max(best, u);
        }
    }

    // guard: near-tie between multisets, or tied/zero magnitudes -> exact path
    bool near = (best - second) < 128u;
    bool tie  = (((t0 ^ t1) & 0xFFFFFFFCu) == 0u) |
                (((t1 ^ t2) & 0xFFFFFFFCu) == 0u) |
                (((t2 ^ t3) & 0xFFFFFFFCu) == 0u) |
                ((t3 & 0xFFFFFFFCu) == 0u);
    bad = near | tie;

    unsigned Mid = best & 7u;
    // bsel bits for multiset ids {3,4,6} -> 0x58; wrong parity flips sign at i_min
    unsigned w = ((0x58u >> Mid) & 1u) ^ parbit;
    // mags-by-rank byte for each multiset id (rank0 in low 2 bits)
    unsigned mcb = __byte_perm(0x01055500u, 0x00060215u, Mid);
    // scatter rank-mags to coordinates via the sort permutation
    unsigned cm = ((mcb)&3u) << (2u * (t0 & 3u));
    cm |= ((mcb >> 2) & 3u) << (2u * (t1 & 3u));
    cm |= ((mcb >> 4) & 3u) << (2u * (t2 & 3u));
    cm |= ((mcb >> 6) & 3u) << (2u * (t3 & 3u));
    // natural signs, with the min coordinate flipped when parity is wrong
    unsigned sbits = (ux0 >> 31) | ((ux1 >> 31) << 1) |
                     ((ux2 >> 31) << 2) | ((ux3 >> 31) << 3);
    sbits ^= w << (t3 & 3u);
    return (int)g_inv.v[cm | (sbits << 8)];
}

template <bool IDX_FLOAT>
__global__ __launch_bounds__(256) void d4_kernel(const float4* __restrict__ X,
                                                 const float4* __restrict__ grid,
                                                 float* __restrict__ out,
                                                 int n) {
    int t = blockIdx.x * blockDim.x + threadIdx.x;
    int j0 = 2 * t;
    int j1 = j0 + 1;
    if (j0 >= n) return;
    bool have1 = (j1 < n);

    float4 x0 = X[j0];
    float4 x1 = have1 ? X[j1] : x0;

    // two independent fast-path instances -> ILP across the dependence spines
    bool bad0, bad1;
    int k0 = fast_kk(x0, bad0);
    int k1 = fast_kk(x1, bad1);
    if (bad0) k0 = slow_exact(x0);
    if (bad1) k1 = slow_exact(x1);

    // winner codeword values read from harness grid -> bit-exact; the two
    // indexed LDGs issue back-to-back and overlap latencies
    float4 v0 = grid[k0];
    float4 v1 = grid[k1];

    float4* ov = reinterpret_cast<float4*>(out);
    ov[j0] = v0;
    if (have1) ov[j1] = v1;

    if (IDX_FLOAT) {
        if (have1) {
            float2 f;
            f.x = (float)k0;
            f.y = (float)k1;
            // j0 even -> 8-byte aligned target
            *reinterpret_cast<float2*>(out + 4LL * n + j0) = f;
        } else {
            out[4LL * n + j0] = (float)k0;
        }
    } else {
        unsigned char* ob = reinterpret_cast<unsigned char*>(out) + 16LL * n;
        if (have1) {
            uchar2 c;
            c.x = (unsigned char)k0;
            c.y = (unsigned char)k1;
            *reinterpret_cast<uchar2*>(ob + j0) = c;
        } else {
            ob[j0] = (unsigned char)k0;
        }
    }
}

extern "C" void kernel_launch(void* const* d_in, const int* in_sizes, int n_in,
                              void* d_out, int out_size) {
    const float4* X    = (const float4*)d_in[0];
    const float4* grid = (const float4*)d_in[1];
    // d_in[2] = grid_norm, unneeded: norms are the exact constants {1,3,5,7,9}

    int n = in_sizes[0] / 4;
    int blocks = (n + 511) / 512;   // 2 vectors per thread

    long long out5 = 5LL * n;
    if ((long long)out_size >= out5) {
        d4_kernel<true><<<blocks, 256>>>(X, grid, (float*)d_out, n);
    } else {
        d4_kernel<false><<<blocks, 256>>>(X, grid, (float*)d_out, n);
    }
}